// round 2
// baseline (speedup 1.0000x reference)
#include <cuda_runtime.h>
#include <math.h>

#define B_SZ 1024
#define H_SZ 1024
#define N_SZ 32
#define K_DIM 1024   // = H
#define N2_DIM 2048  // = 2H

// Scratch (device globals: no allocation allowed in kernel_launch)
__device__ float g_ybuf[B_SZ * H_SZ];            // gelu(y + u*D)  [B,H]
__device__ float g_z[B_SZ * N2_DIM];             // z = y@W.T + b  [B,2H]

// ---------------------------------------------------------------------------
// Kernel 1: complex diag state update + C-readout + GELU skip.
// 8 threads per (b,h) row, each handles 4 of the N=32 state entries via float4.
// ---------------------------------------------------------------------------
__global__ __launch_bounds__(256) void s4_update_kernel(
    const float* __restrict__ u,
    const float* __restrict__ sre, const float* __restrict__ sim,
    const float* __restrict__ dAr, const float* __restrict__ dAi,
    const float* __restrict__ dBr, const float* __restrict__ dBi,
    const float* __restrict__ Cr,  const float* __restrict__ Ci,
    const float* __restrict__ D,
    float* __restrict__ ns_re, float* __restrict__ ns_im)
{
    int tid = blockIdx.x * 256 + threadIdx.x;
    int row = tid >> 3;        // (b*H + h)
    int sub = tid & 7;         // which group of 4 n's
    int h   = row & (H_SZ - 1);

    long soff = (long)row * N_SZ + sub * 4;
    long poff = (long)h   * N_SZ + sub * 4;

    float4 s_re = *(const float4*)(sre + soff);
    float4 s_im = *(const float4*)(sim + soff);
    float4 ar   = *(const float4*)(dAr + poff);
    float4 ai   = *(const float4*)(dAi + poff);
    float4 br   = *(const float4*)(dBr + poff);
    float4 bi   = *(const float4*)(dBi + poff);
    float4 cr   = *(const float4*)(Cr  + poff);
    float4 ci   = *(const float4*)(Ci  + poff);
    float  uv   = u[row];

    float4 nr, ni;
    nr.x = ar.x * s_re.x - ai.x * s_im.x + br.x * uv;
    nr.y = ar.y * s_re.y - ai.y * s_im.y + br.y * uv;
    nr.z = ar.z * s_re.z - ai.z * s_im.z + br.z * uv;
    nr.w = ar.w * s_re.w - ai.w * s_im.w + br.w * uv;
    ni.x = ar.x * s_im.x + ai.x * s_re.x + bi.x * uv;
    ni.y = ar.y * s_im.y + ai.y * s_re.y + bi.y * uv;
    ni.z = ar.z * s_im.z + ai.z * s_re.z + bi.z * uv;
    ni.w = ar.w * s_im.w + ai.w * s_re.w + bi.w * uv;

    *(float4*)(ns_re + soff) = nr;
    *(float4*)(ns_im + soff) = ni;

    float acc = cr.x * nr.x - ci.x * ni.x
              + cr.y * nr.y - ci.y * ni.y
              + cr.z * nr.z - ci.z * ni.z
              + cr.w * nr.w - ci.w * ni.w;

    // reduce across the 8 lanes of this row (lanes are contiguous in the warp)
    acc += __shfl_xor_sync(0xffffffffu, acc, 4);
    acc += __shfl_xor_sync(0xffffffffu, acc, 2);
    acc += __shfl_xor_sync(0xffffffffu, acc, 1);

    if (sub == 0) {
        float y = 2.0f * acc + uv * D[h];
        // exact GELU: x * 0.5 * (1 + erf(x / sqrt(2)))
        float g = 0.5f * y * (1.0f + erff(y * 0.70710678118654752f));
        g_ybuf[row] = g;
    }
}

// ---------------------------------------------------------------------------
// Kernel 2: SGEMM (NT): z[M, 2H] = ybuf[M, K] @ W[2H, K]^T + bias
// 128x128x16 tile, 256 threads, 8x8 microtile per thread.
// ---------------------------------------------------------------------------
#define BM 128
#define BN 128
#define BK 16

__global__ __launch_bounds__(256) void gemm_kernel(
    const float* __restrict__ Bw,   // W: [2H, K] row-major
    const float* __restrict__ bias) // b: [2H]
{
    __shared__ float As[BK][BM + 4];
    __shared__ float Bs[BK][BN + 4];

    const float* A = g_ybuf;
    int tid = threadIdx.x;
    int bm = blockIdx.y * BM;
    int bn = blockIdx.x * BN;
    int tx = tid & 15;   // N dir
    int ty = tid >> 4;   // M dir

    float acc[8][8];
#pragma unroll
    for (int i = 0; i < 8; i++)
#pragma unroll
        for (int j = 0; j < 8; j++) acc[i][j] = 0.0f;

    for (int k0 = 0; k0 < K_DIM; k0 += BK) {
#pragma unroll
        for (int i = 0; i < 2; i++) {
            int lid = tid * 2 + i;     // 0..511
            int m   = lid >> 2;        // 0..127
            int kq  = lid & 3;         // which float4 along K
            float4 va = *(const float4*)(A  + (long)(bm + m) * K_DIM + k0 + kq * 4);
            As[kq * 4 + 0][m] = va.x;
            As[kq * 4 + 1][m] = va.y;
            As[kq * 4 + 2][m] = va.z;
            As[kq * 4 + 3][m] = va.w;
            float4 vb = *(const float4*)(Bw + (long)(bn + m) * K_DIM + k0 + kq * 4);
            Bs[kq * 4 + 0][m] = vb.x;
            Bs[kq * 4 + 1][m] = vb.y;
            Bs[kq * 4 + 2][m] = vb.z;
            Bs[kq * 4 + 3][m] = vb.w;
        }
        __syncthreads();

#pragma unroll
        for (int kk = 0; kk < BK; kk++) {
            float a[8], bf[8];
            *(float4*)(a)      = *(const float4*)&As[kk][ty * 8];
            *(float4*)(a + 4)  = *(const float4*)&As[kk][ty * 8 + 4];
            *(float4*)(bf)     = *(const float4*)&Bs[kk][tx * 8];
            *(float4*)(bf + 4) = *(const float4*)&Bs[kk][tx * 8 + 4];
#pragma unroll
            for (int i = 0; i < 8; i++)
#pragma unroll
                for (int j = 0; j < 8; j++)
                    acc[i][j] += a[i] * bf[j];
        }
        __syncthreads();
    }

#pragma unroll
    for (int i = 0; i < 8; i++) {
        int m = bm + ty * 8 + i;
#pragma unroll
        for (int j = 0; j < 8; j += 4) {
            int n = bn + tx * 8 + j;
            float4 o;
            o.x = acc[i][j + 0] + bias[n + 0];
            o.y = acc[i][j + 1] + bias[n + 1];
            o.z = acc[i][j + 2] + bias[n + 2];
            o.w = acc[i][j + 3] + bias[n + 3];
            *(float4*)(g_z + (long)m * N2_DIM + n) = o;
        }
    }
}

// ---------------------------------------------------------------------------
// Kernel 3: GLU:  y_out[b, j] = z[b, j] * sigmoid(z[b, j + H])
// ---------------------------------------------------------------------------
__global__ __launch_bounds__(256) void glu_kernel(float* __restrict__ out)
{
    int i = blockIdx.x * 256 + threadIdx.x;   // over B*H/4
    int b = i >> 8;                           // 256 float4 per row of H
    int j = i & 255;
    float4 a = *(const float4*)(g_z + (long)b * N2_DIM + j * 4);
    float4 g = *(const float4*)(g_z + (long)b * N2_DIM + H_SZ + j * 4);
    float4 o;
    o.x = a.x / (1.0f + __expf(-g.x) * 0.0f + expf(-g.x) * 1.0f);
    // (use precise expf for all lanes)
    o.x = a.x / (1.0f + expf(-g.x));
    o.y = a.y / (1.0f + expf(-g.y));
    o.z = a.z / (1.0f + expf(-g.z));
    o.w = a.w / (1.0f + expf(-g.w));
    *(float4*)(out + (long)b * H_SZ + j * 4) = o;
}

// ---------------------------------------------------------------------------
extern "C" void kernel_launch(void* const* d_in, const int* in_sizes, int n_in,
                              void* d_out, int out_size)
{
    const float* u        = (const float*)d_in[0];
    const float* state_re = (const float*)d_in[1];
    const float* state_im = (const float*)d_in[2];
    const float* dA_re    = (const float*)d_in[3];
    const float* dA_im    = (const float*)d_in[4];
    const float* dB_re    = (const float*)d_in[5];
    const float* dB_im    = (const float*)d_in[6];
    const float* C_re     = (const float*)d_in[7];
    const float* C_im     = (const float*)d_in[8];
    const float* D        = (const float*)d_in[9];
    const float* W        = (const float*)d_in[10];
    const float* bias     = (const float*)d_in[11];

    float* out = (float*)d_out;
    float* y_out = out;                                   // [B, H]
    float* ns_re = out + (long)B_SZ * H_SZ;               // [B, H, N]
    float* ns_im = ns_re + (long)B_SZ * H_SZ * N_SZ;      // [B, H, N]

    // Kernel 1: state update + readout + gelu -> g_ybuf
    {
        int total = B_SZ * H_SZ * 8;
        s4_update_kernel<<<total / 256, 256>>>(
            u, state_re, state_im, dA_re, dA_im, dB_re, dB_im,
            C_re, C_im, D, ns_re, ns_im);
    }

    // Kernel 2: z = ybuf @ W^T + b
    {
        dim3 grid(N2_DIM / BN, B_SZ / BM);   // (16, 8)
        gemm_kernel<<<grid, 256>>>(W, bias);
    }

    // Kernel 3: GLU -> y_out
    {
        int total = B_SZ * H_SZ / 4;
        glu_kernel<<<total / 256, 256>>>(y_out);
    }
}

// round 7
// speedup vs baseline: 1.5486x; 1.5486x over previous
#include <cuda_runtime.h>
#include <cuda_bf16.h>
#include <math.h>
#include <stdint.h>

#define B_SZ 1024
#define H_SZ 1024
#define N_SZ 32
#define K_DIM 1024   // = H
#define N2_DIM 2048  // = 2H

// ---------------------------------------------------------------------------
// Scratch (device globals: no allocation allowed)
// ---------------------------------------------------------------------------
__device__ __nv_bfloat16 g_yh[B_SZ * H_SZ];       // hi(gelu(y+uD))
__device__ __nv_bfloat16 g_yl[B_SZ * H_SZ];       // lo residual
__device__ __nv_bfloat16 g_wh[N2_DIM * K_DIM];    // hi(W)
__device__ __nv_bfloat16 g_wl[N2_DIM * K_DIM];    // lo residual
__device__ float         g_z [B_SZ * N2_DIM];     // z (pre-bias)

// ---------------------------------------------------------------------------
// Kernel 1: complex diag state update + C-readout + GELU skip -> bf16 hi/lo
// 8 threads per (b,h) row, float4 per thread over N=32.
// ---------------------------------------------------------------------------
__global__ __launch_bounds__(256) void s4_update_kernel(
    const float* __restrict__ u,
    const float* __restrict__ sre, const float* __restrict__ sim,
    const float* __restrict__ dAr, const float* __restrict__ dAi,
    const float* __restrict__ dBr, const float* __restrict__ dBi,
    const float* __restrict__ Cr,  const float* __restrict__ Ci,
    const float* __restrict__ D,
    float* __restrict__ ns_re, float* __restrict__ ns_im)
{
    int tid = blockIdx.x * 256 + threadIdx.x;
    int row = tid >> 3;
    int sub = tid & 7;
    int h   = row & (H_SZ - 1);

    long soff = (long)row * N_SZ + sub * 4;
    long poff = (long)h   * N_SZ + sub * 4;

    float4 s_re = *(const float4*)(sre + soff);
    float4 s_im = *(const float4*)(sim + soff);
    float4 ar   = *(const float4*)(dAr + poff);
    float4 ai   = *(const float4*)(dAi + poff);
    float4 br   = *(const float4*)(dBr + poff);
    float4 bi   = *(const float4*)(dBi + poff);
    float4 cr   = *(const float4*)(Cr  + poff);
    float4 ci   = *(const float4*)(Ci  + poff);
    float  uv   = u[row];

    float4 nr, ni;
    nr.x = ar.x * s_re.x - ai.x * s_im.x + br.x * uv;
    nr.y = ar.y * s_re.y - ai.y * s_im.y + br.y * uv;
    nr.z = ar.z * s_re.z - ai.z * s_im.z + br.z * uv;
    nr.w = ar.w * s_re.w - ai.w * s_im.w + br.w * uv;
    ni.x = ar.x * s_im.x + ai.x * s_re.x + bi.x * uv;
    ni.y = ar.y * s_im.y + ai.y * s_re.y + bi.y * uv;
    ni.z = ar.z * s_im.z + ai.z * s_re.z + bi.z * uv;
    ni.w = ar.w * s_im.w + ai.w * s_re.w + bi.w * uv;

    *(float4*)(ns_re + soff) = nr;
    *(float4*)(ns_im + soff) = ni;

    float acc = cr.x * nr.x - ci.x * ni.x
              + cr.y * nr.y - ci.y * ni.y
              + cr.z * nr.z - ci.z * ni.z
              + cr.w * nr.w - ci.w * ni.w;

    acc += __shfl_xor_sync(0xffffffffu, acc, 4);
    acc += __shfl_xor_sync(0xffffffffu, acc, 2);
    acc += __shfl_xor_sync(0xffffffffu, acc, 1);

    if (sub == 0) {
        float y = 2.0f * acc + uv * D[h];
        float g = 0.5f * y * (1.0f + erff(y * 0.70710678118654752f));
        __nv_bfloat16 hi = __float2bfloat16_rn(g);
        g_yh[row] = hi;
        g_yl[row] = __float2bfloat16_rn(g - __bfloat162float(hi));
    }
}

// ---------------------------------------------------------------------------
// Kernel 1b: split W into bf16 hi/lo.  8 elems per thread.
// ---------------------------------------------------------------------------
__global__ __launch_bounds__(256) void convert_w_kernel(const float* __restrict__ W)
{
    int i = blockIdx.x * 256 + threadIdx.x;        // over 2M/8 groups
    const float4* w4 = (const float4*)W + (long)i * 2;
    float4 a = w4[0], b = w4[1];
    float v[8] = {a.x, a.y, a.z, a.w, b.x, b.y, b.z, b.w};

    __nv_bfloat16 h[8], l[8];
#pragma unroll
    for (int j = 0; j < 8; j++) {
        h[j] = __float2bfloat16_rn(v[j]);
        l[j] = __float2bfloat16_rn(v[j] - __bfloat162float(h[j]));
    }
    *(uint4*)(g_wh + (long)i * 8) = *(uint4*)h;
    *(uint4*)(g_wl + (long)i * 8) = *(uint4*)l;
}

// ---------------------------------------------------------------------------
// Kernel 2: bf16 split tensor-core GEMM (TN):  z = y @ W^T
// CTA tile 128x128, K-chunk 64, 8 warps (2x4), warp tile 64x32.
// 3 passes per chunk: Ah*Bh + Al*Bh + Ah*Bl  (fp32 accumulate).
// ---------------------------------------------------------------------------
__device__ __forceinline__ void ldsm_x4(uint32_t& r0, uint32_t& r1,
                                        uint32_t& r2, uint32_t& r3, uint32_t addr)
{
    asm volatile("ldmatrix.sync.aligned.m8n8.x4.shared.b16 {%0,%1,%2,%3}, [%4];\n"
                 : "=r"(r0), "=r"(r1), "=r"(r2), "=r"(r3) : "r"(addr));
}

__device__ __forceinline__ void mma_16816(float* c, const uint32_t* a,
                                          uint32_t b0, uint32_t b1)
{
    asm volatile(
        "mma.sync.aligned.m16n8k16.row.col.f32.bf16.bf16.f32 "
        "{%0,%1,%2,%3}, {%4,%5,%6,%7}, {%8,%9}, {%0,%1,%2,%3};\n"
        : "+f"(c[0]), "+f"(c[1]), "+f"(c[2]), "+f"(c[3])
        : "r"(a[0]), "r"(a[1]), "r"(a[2]), "r"(a[3]), "r"(b0), "r"(b1));
}

#define GBK 64
// smem layout (bytes): Ah[0,16K) Al[16K,32K) Bh[32K,48K) Bl[48K,64K)
#define SM_AH 0
#define SM_AL 16384
#define SM_BH 32768
#define SM_BL 49152
#define SM_TOTAL 65536

__global__ __launch_bounds__(256) void gemm_bf16_kernel()
{
    extern __shared__ char smem[];
    uint32_t sbase = (uint32_t)__cvta_generic_to_shared(smem);

    int tid  = threadIdx.x;
    int lane = tid & 31;
    int wid  = tid >> 5;
    int wm   = (wid & 1) * 64;     // warp M offset in tile
    int wn   = (wid >> 1) * 32;    // warp N offset in tile
    int bm   = blockIdx.y * 128;
    int bn   = blockIdx.x * 128;

    float acc[4][4][4];
#pragma unroll
    for (int mi = 0; mi < 4; mi++)
#pragma unroll
        for (int ni = 0; ni < 4; ni++)
#pragma unroll
            for (int r = 0; r < 4; r++) acc[mi][ni][r] = 0.0f;

    // precomputed frag-load geometry
    int a_row_in_frag = ((lane & 8) ? 8 : 0) + (lane & 7);   // + mi*16 + wm
    int a_chalf       = (lane >> 4);                          // k half (0/1)
    int b_row_in_frag = ((lane & 16) ? 8 : 0) + (lane & 7);   // + pi*16 + wn
    int b_chalf       = ((lane >> 3) & 1);

    for (int k0 = 0; k0 < K_DIM; k0 += GBK) {
        __syncthreads();
        // ---- load 4 tiles: 128 rows x 64 bf16 each, SW-swizzled ----
#pragma unroll
        for (int i = 0; i < 4; i++) {
            int lid = tid + i * 256;          // 0..1023
            int r   = lid >> 3;
            int c   = lid & 7;
            int sw  = ((c ^ (r & 7)) << 4) + r * 128;
            long ga = (long)(bm + r) * K_DIM + k0 + c * 8;
            long gb = (long)(bn + r) * K_DIM + k0 + c * 8;
            *(uint4*)(smem + SM_AH + sw) = *(const uint4*)(g_yh + ga);
            *(uint4*)(smem + SM_AL + sw) = *(const uint4*)(g_yl + ga);
            *(uint4*)(smem + SM_BH + sw) = *(const uint4*)(g_wh + gb);
            *(uint4*)(smem + SM_BL + sw) = *(const uint4*)(g_wl + gb);
        }
        __syncthreads();

#pragma unroll
        for (int term = 0; term < 3; term++) {
            uint32_t abase = sbase + (term == 1 ? SM_AL : SM_AH);
            uint32_t bbase = sbase + (term == 2 ? SM_BL : SM_BH);
#pragma unroll
            for (int ks = 0; ks < 4; ks++) {
                uint32_t af[4][4];
#pragma unroll
                for (int mi = 0; mi < 4; mi++) {
                    int arow = wm + mi * 16 + a_row_in_frag;
                    int ac   = ks * 2 + a_chalf;
                    ldsm_x4(af[mi][0], af[mi][1], af[mi][2], af[mi][3],
                            abase + arow * 128 + ((ac ^ (arow & 7)) << 4));
                }
                uint32_t bfr[2][4];
#pragma unroll
                for (int pi = 0; pi < 2; pi++) {
                    int brow = wn + pi * 16 + b_row_in_frag;
                    int bc   = ks * 2 + b_chalf;
                    ldsm_x4(bfr[pi][0], bfr[pi][1], bfr[pi][2], bfr[pi][3],
                            bbase + brow * 128 + ((bc ^ (brow & 7)) << 4));
                }
#pragma unroll
                for (int mi = 0; mi < 4; mi++)
#pragma unroll
                    for (int ni = 0; ni < 4; ni++) {
                        int pi = ni >> 1, sel = (ni & 1) * 2;
                        mma_16816(acc[mi][ni], af[mi],
                                  bfr[pi][sel + 0], bfr[pi][sel + 1]);
                    }
            }
        }
    }

    // ---- epilogue: store raw z ----
#pragma unroll
    for (int mi = 0; mi < 4; mi++) {
#pragma unroll
        for (int ni = 0; ni < 4; ni++) {
            int r0  = bm + wm + mi * 16 + (lane >> 2);
            int col = bn + wn + ni * 8 + (lane & 3) * 2;
            float2 v0 = make_float2(acc[mi][ni][0], acc[mi][ni][1]);
            float2 v1 = make_float2(acc[mi][ni][2], acc[mi][ni][3]);
            *(float2*)(g_z + (long)r0 * N2_DIM + col)       = v0;
            *(float2*)(g_z + (long)(r0 + 8) * N2_DIM + col) = v1;
        }
    }
}

// ---------------------------------------------------------------------------
// Kernel 3: bias + GLU:  y_out[b,j] = (z[b,j]+b[j]) * sigmoid(z[b,j+H]+b[j+H])
// ---------------------------------------------------------------------------
__global__ __launch_bounds__(256) void glu_kernel(
    const float* __restrict__ bias, float* __restrict__ out)
{
    int i = blockIdx.x * 256 + threadIdx.x;   // over B*H/4
    int b = i >> 8;
    int j = (i & 255) * 4;
    float4 a  = *(const float4*)(g_z + (long)b * N2_DIM + j);
    float4 g  = *(const float4*)(g_z + (long)b * N2_DIM + H_SZ + j);
    float4 ba = *(const float4*)(bias + j);
    float4 bg = *(const float4*)(bias + H_SZ + j);
    float4 o;
    o.x = (a.x + ba.x) / (1.0f + expf(-(g.x + bg.x)));
    o.y = (a.y + ba.y) / (1.0f + expf(-(g.y + bg.y)));
    o.z = (a.z + ba.z) / (1.0f + expf(-(g.z + bg.z)));
    o.w = (a.w + ba.w) / (1.0f + expf(-(g.w + bg.w)));
    *(float4*)(out + (long)b * H_SZ + j) = o;
}

// ---------------------------------------------------------------------------
extern "C" void kernel_launch(void* const* d_in, const int* in_sizes, int n_in,
                              void* d_out, int out_size)
{
    const float* u        = (const float*)d_in[0];
    const float* state_re = (const float*)d_in[1];
    const float* state_im = (const float*)d_in[2];
    const float* dA_re    = (const float*)d_in[3];
    const float* dA_im    = (const float*)d_in[4];
    const float* dB_re    = (const float*)d_in[5];
    const float* dB_im    = (const float*)d_in[6];
    const float* C_re     = (const float*)d_in[7];
    const float* C_im     = (const float*)d_in[8];
    const float* D        = (const float*)d_in[9];
    const float* W        = (const float*)d_in[10];
    const float* bias     = (const float*)d_in[11];

    float* out   = (float*)d_out;
    float* y_out = out;                                   // [B, H]
    float* ns_re = out + (long)B_SZ * H_SZ;               // [B, H, N]
    float* ns_im = ns_re + (long)B_SZ * H_SZ * N_SZ;      // [B, H, N]

    static bool attr_set = false;
    if (!attr_set) {
        cudaFuncSetAttribute(gemm_bf16_kernel,
                             cudaFuncAttributeMaxDynamicSharedMemorySize, SM_TOTAL);
        attr_set = true;
    }

    // 1: state update + readout + gelu -> g_yh/g_yl (and ns outputs)
    s4_update_kernel<<<B_SZ * H_SZ * 8 / 256, 256>>>(
        u, state_re, state_im, dA_re, dA_im, dB_re, dB_im,
        C_re, C_im, D, ns_re, ns_im);

    // 1b: W -> bf16 hi/lo
    convert_w_kernel<<<(N2_DIM * K_DIM / 8) / 256, 256>>>(W);

    // 2: z = y @ W^T (split bf16 tensor cores)
    {
        dim3 grid(N2_DIM / 128, B_SZ / 128);   // (16, 8)
        gemm_bf16_kernel<<<grid, 256, SM_TOTAL>>>();
    }

    // 3: bias + GLU -> y_out
    glu_kernel<<<B_SZ * H_SZ / 4 / 256, 256>>>(bias, y_out);
}

// round 8
// speedup vs baseline: 1.6872x; 1.0895x over previous
#include <cuda_runtime.h>
#include <cuda_bf16.h>
#include <math.h>
#include <stdint.h>

#define B_SZ 1024
#define H_SZ 1024
#define N_SZ 32
#define K_DIM 1024   // = H
#define N2_DIM 2048  // = 2H

// ---------------------------------------------------------------------------
// Scratch (device globals: no allocation allowed)
// ---------------------------------------------------------------------------
__device__ __nv_bfloat16 g_yh[B_SZ * H_SZ];       // hi(gelu(y+uD))
__device__ __nv_bfloat16 g_yl[B_SZ * H_SZ];       // lo residual

// ---------------------------------------------------------------------------
// Kernel 1: complex diag state update + C-readout + GELU skip -> bf16 hi/lo
// 8 threads per (b,h) row, float4 per thread over N=32.  (near HBM floor)
// ---------------------------------------------------------------------------
__global__ __launch_bounds__(256) void s4_update_kernel(
    const float* __restrict__ u,
    const float* __restrict__ sre, const float* __restrict__ sim,
    const float* __restrict__ dAr, const float* __restrict__ dAi,
    const float* __restrict__ dBr, const float* __restrict__ dBi,
    const float* __restrict__ Cr,  const float* __restrict__ Ci,
    const float* __restrict__ D,
    float* __restrict__ ns_re, float* __restrict__ ns_im)
{
    int tid = blockIdx.x * 256 + threadIdx.x;
    int row = tid >> 3;
    int sub = tid & 7;
    int h   = row & (H_SZ - 1);

    long soff = (long)row * N_SZ + sub * 4;
    long poff = (long)h   * N_SZ + sub * 4;

    float4 s_re = *(const float4*)(sre + soff);
    float4 s_im = *(const float4*)(sim + soff);
    float4 ar   = *(const float4*)(dAr + poff);
    float4 ai   = *(const float4*)(dAi + poff);
    float4 br   = *(const float4*)(dBr + poff);
    float4 bi   = *(const float4*)(dBi + poff);
    float4 cr   = *(const float4*)(Cr  + poff);
    float4 ci   = *(const float4*)(Ci  + poff);
    float  uv   = u[row];

    float4 nr, ni;
    nr.x = ar.x * s_re.x - ai.x * s_im.x + br.x * uv;
    nr.y = ar.y * s_re.y - ai.y * s_im.y + br.y * uv;
    nr.z = ar.z * s_re.z - ai.z * s_im.z + br.z * uv;
    nr.w = ar.w * s_re.w - ai.w * s_im.w + br.w * uv;
    ni.x = ar.x * s_im.x + ai.x * s_re.x + bi.x * uv;
    ni.y = ar.y * s_im.y + ai.y * s_re.y + bi.y * uv;
    ni.z = ar.z * s_im.z + ai.z * s_re.z + bi.z * uv;
    ni.w = ar.w * s_im.w + ai.w * s_re.w + bi.w * uv;

    *(float4*)(ns_re + soff) = nr;
    *(float4*)(ns_im + soff) = ni;

    float acc = cr.x * nr.x - ci.x * ni.x
              + cr.y * nr.y - ci.y * ni.y
              + cr.z * nr.z - ci.z * ni.z
              + cr.w * nr.w - ci.w * ni.w;

    acc += __shfl_xor_sync(0xffffffffu, acc, 4);
    acc += __shfl_xor_sync(0xffffffffu, acc, 2);
    acc += __shfl_xor_sync(0xffffffffu, acc, 1);

    if (sub == 0) {
        float y = 2.0f * acc + uv * D[h];
        float g = 0.5f * y * (1.0f + erff(y * 0.70710678118654752f));
        __nv_bfloat16 hi = __float2bfloat16_rn(g);
        g_yh[row] = hi;
        g_yl[row] = __float2bfloat16_rn(g - __bfloat162float(hi));
    }
}

// ---------------------------------------------------------------------------
// Kernel 2 (fused): split-bf16 tensor GEMM + bias + GLU -> y_out
//
// CTA: M-tile 128, paired N columns: [bn64, bn64+64) and [1024+bn64, +64)
// (combined 128 "B rows").  K-chunk 64, 16 chunks, 2-stage cp.async pipeline.
// A (g_yh/g_yl bf16) via cp.async; W fp32 register-prefetched one chunk
// ahead, split hi/lo in registers, STS after compute.  3-term split MMA.
// Epilogue stages z in smem and applies bias + GLU directly.
// ---------------------------------------------------------------------------
__device__ __forceinline__ void ldsm_x4(uint32_t& r0, uint32_t& r1,
                                        uint32_t& r2, uint32_t& r3, uint32_t addr)
{
    asm volatile("ldmatrix.sync.aligned.m8n8.x4.shared.b16 {%0,%1,%2,%3}, [%4];\n"
                 : "=r"(r0), "=r"(r1), "=r"(r2), "=r"(r3) : "r"(addr));
}

__device__ __forceinline__ void mma_16816(float* c, const uint32_t* a,
                                          uint32_t b0, uint32_t b1)
{
    asm volatile(
        "mma.sync.aligned.m16n8k16.row.col.f32.bf16.bf16.f32 "
        "{%0,%1,%2,%3}, {%4,%5,%6,%7}, {%8,%9}, {%0,%1,%2,%3};\n"
        : "+f"(c[0]), "+f"(c[1]), "+f"(c[2]), "+f"(c[3])
        : "r"(a[0]), "r"(a[1]), "r"(a[2]), "r"(a[3]), "r"(b0), "r"(b1));
}

__device__ __forceinline__ void cp_async16(uint32_t dst, const void* src)
{
    asm volatile("cp.async.cg.shared.global [%0], [%1], 16;\n"
                 :: "r"(dst), "l"(src));
}

#define GBK   64
#define SM_AH 0
#define SM_AL 16384
#define SM_BH 32768
#define SM_BL 49152
#define STAGE 65536
#define SM_TOTAL (2 * STAGE)
#define ZS_STRIDE 132   // fp32 z staging stride (conflict-breaking)

__global__ __launch_bounds__(256) void gemm_fused_kernel(
    const float* __restrict__ W,
    const float* __restrict__ bias,
    float* __restrict__ y_out)
{
    extern __shared__ char smem[];
    uint32_t sbase = (uint32_t)__cvta_generic_to_shared(smem);

    int tid  = threadIdx.x;
    int lane = tid & 31;
    int wid  = tid >> 5;
    int wm   = (wid & 1) * 64;
    int wn   = (wid >> 1) * 32;
    int bm   = blockIdx.y * 128;
    int bn64 = blockIdx.x * 64;    // first-half column base

    float acc[4][4][4];
#pragma unroll
    for (int mi = 0; mi < 4; mi++)
#pragma unroll
        for (int ni = 0; ni < 4; ni++)
#pragma unroll
            for (int r = 0; r < 4; r++) acc[mi][ni][r] = 0.0f;

    int a_row_in_frag = ((lane & 8) ? 8 : 0) + (lane & 7);
    int a_chalf       = (lane >> 4);
    int b_row_in_frag = ((lane & 16) ? 8 : 0) + (lane & 7);
    int b_chalf       = ((lane >> 3) & 1);

    float4 wreg[8];   // W fp32 prefetch (one K-chunk)

    auto issueA = [&](int k0, int buf) {
        uint32_t st = sbase + buf * STAGE;
#pragma unroll
        for (int i = 0; i < 4; i++) {
            int lid = tid + i * 256;
            int r   = lid >> 3;
            int c   = lid & 7;
            int sw  = ((c ^ (r & 7)) << 4) + r * 128;
            long ga = (long)(bm + r) * K_DIM + k0 + c * 8;
            cp_async16(st + SM_AH + sw, g_yh + ga);
            cp_async16(st + SM_AL + sw, g_yl + ga);
        }
        asm volatile("cp.async.commit_group;\n" ::: "memory");
    };

    auto issueW = [&](int k0) {
#pragma unroll
        for (int i = 0; i < 4; i++) {
            int p    = tid + i * 256;
            int row  = p >> 3;
            int c8   = p & 7;
            int grow = (row < 64) ? (bn64 + row) : (960 + bn64 + row);
            const float* src = W + (long)grow * K_DIM + k0 + c8 * 8;
            wreg[2 * i]     = *(const float4*)src;
            wreg[2 * i + 1] = *(const float4*)(src + 4);
        }
    };

    auto stsW = [&](int buf) {
        char* st = smem + buf * STAGE;
#pragma unroll
        for (int i = 0; i < 4; i++) {
            int p   = tid + i * 256;
            int row = p >> 3;
            int c8  = p & 7;
            int sw  = ((c8 ^ (row & 7)) << 4) + row * 128;
            const float* v = (const float*)&wreg[2 * i];
            __nv_bfloat16 h[8], l[8];
#pragma unroll
            for (int j = 0; j < 8; j++) {
                h[j] = __float2bfloat16_rn(v[j]);
                l[j] = __float2bfloat16_rn(v[j] - __bfloat162float(h[j]));
            }
            *(uint4*)(st + SM_BH + sw) = *(uint4*)h;
            *(uint4*)(st + SM_BL + sw) = *(uint4*)l;
        }
    };

    auto compute = [&](int buf) {
        uint32_t st = sbase + buf * STAGE;
#pragma unroll
        for (int term = 0; term < 3; term++) {
            uint32_t abase = st + (term == 1 ? SM_AL : SM_AH);
            uint32_t bbase = st + (term == 2 ? SM_BL : SM_BH);
#pragma unroll
            for (int ks = 0; ks < 4; ks++) {
                uint32_t af[4][4];
#pragma unroll
                for (int mi = 0; mi < 4; mi++) {
                    int arow = wm + mi * 16 + a_row_in_frag;
                    int ac   = ks * 2 + a_chalf;
                    ldsm_x4(af[mi][0], af[mi][1], af[mi][2], af[mi][3],
                            abase + arow * 128 + ((ac ^ (arow & 7)) << 4));
                }
                uint32_t bfr[2][4];
#pragma unroll
                for (int pi = 0; pi < 2; pi++) {
                    int brow = wn + pi * 16 + b_row_in_frag;
                    int bc   = ks * 2 + b_chalf;
                    ldsm_x4(bfr[pi][0], bfr[pi][1], bfr[pi][2], bfr[pi][3],
                            bbase + brow * 128 + ((bc ^ (brow & 7)) << 4));
                }
#pragma unroll
                for (int mi = 0; mi < 4; mi++)
#pragma unroll
                    for (int ni = 0; ni < 4; ni++) {
                        int pi = ni >> 1, sel = (ni & 1) * 2;
                        mma_16816(acc[mi][ni], af[mi],
                                  bfr[pi][sel + 0], bfr[pi][sel + 1]);
                    }
            }
        }
    };

    // ---- pipelined mainloop ----
    issueW(0);
    issueA(0, 0);
    stsW(0);

    int buf = 0;
#pragma unroll 1
    for (int c = 0; c < 16; c++) {
        if (c < 15) {
            int k0n = (c + 1) * GBK;
            issueW(k0n);
            issueA(k0n, buf ^ 1);
            asm volatile("cp.async.wait_group 1;\n" ::: "memory");
        } else {
            asm volatile("cp.async.wait_group 0;\n" ::: "memory");
        }
        __syncthreads();
        compute(buf);
        if (c < 15) stsW(buf ^ 1);
        __syncthreads();
        buf ^= 1;
    }

    // ---- epilogue: stage z in smem, apply bias + GLU, write y_out ----
    float* zs = (float*)smem;
#pragma unroll
    for (int mi = 0; mi < 4; mi++) {
#pragma unroll
        for (int ni = 0; ni < 4; ni++) {
            int r0  = wm + mi * 16 + (lane >> 2);
            int col = wn + ni * 8 + (lane & 3) * 2;
            zs[r0 * ZS_STRIDE + col]           = acc[mi][ni][0];
            zs[r0 * ZS_STRIDE + col + 1]       = acc[mi][ni][1];
            zs[(r0 + 8) * ZS_STRIDE + col]     = acc[mi][ni][2];
            zs[(r0 + 8) * ZS_STRIDE + col + 1] = acc[mi][ni][3];
        }
    }
    __syncthreads();

#pragma unroll
    for (int i = 0; i < 8; i++) {
        int idx = tid + i * 256;          // 0..2047: one float4 group each
        int m   = idx >> 4;               // 0..127
        int j4  = (idx & 15) * 4;         // 0..60
        float4 z1 = *(float4*)(zs + m * ZS_STRIDE + j4);
        float4 z2 = *(float4*)(zs + m * ZS_STRIDE + 64 + j4);
        float4 b1 = *(const float4*)(bias + bn64 + j4);
        float4 b2 = *(const float4*)(bias + 1024 + bn64 + j4);
        float4 o;
        o.x = (z1.x + b1.x) / (1.0f + expf(-(z2.x + b2.x)));
        o.y = (z1.y + b1.y) / (1.0f + expf(-(z2.y + b2.y)));
        o.z = (z1.z + b1.z) / (1.0f + expf(-(z2.z + b2.z)));
        o.w = (z1.w + b1.w) / (1.0f + expf(-(z2.w + b2.w)));
        *(float4*)(y_out + (long)(bm + m) * H_SZ + bn64 + j4) = o;
    }
}

// ---------------------------------------------------------------------------
extern "C" void kernel_launch(void* const* d_in, const int* in_sizes, int n_in,
                              void* d_out, int out_size)
{
    const float* u        = (const float*)d_in[0];
    const float* state_re = (const float*)d_in[1];
    const float* state_im = (const float*)d_in[2];
    const float* dA_re    = (const float*)d_in[3];
    const float* dA_im    = (const float*)d_in[4];
    const float* dB_re    = (const float*)d_in[5];
    const float* dB_im    = (const float*)d_in[6];
    const float* C_re     = (const float*)d_in[7];
    const float* C_im     = (const float*)d_in[8];
    const float* D        = (const float*)d_in[9];
    const float* W        = (const float*)d_in[10];
    const float* bias     = (const float*)d_in[11];

    float* out   = (float*)d_out;
    float* y_out = out;                                   // [B, H]
    float* ns_re = out + (long)B_SZ * H_SZ;               // [B, H, N]
    float* ns_im = ns_re + (long)B_SZ * H_SZ * N_SZ;      // [B, H, N]

    static bool attr_set = false;
    if (!attr_set) {
        cudaFuncSetAttribute(gemm_fused_kernel,
                             cudaFuncAttributeMaxDynamicSharedMemorySize, SM_TOTAL);
        attr_set = true;
    }

    // 1: state update + readout + gelu -> g_yh/g_yl (and ns outputs)
    s4_update_kernel<<<B_SZ * H_SZ * 8 / 256, 256>>>(
        u, state_re, state_im, dA_re, dA_im, dB_re, dB_im,
        C_re, C_im, D, ns_re, ns_im);

    // 2: fused GEMM + bias + GLU -> y_out
    {
        dim3 grid(16, 8);   // 16 paired-column tiles x 8 M tiles = 128 CTAs
        gemm_fused_kernel<<<grid, 256, SM_TOTAL>>>(W, bias, y_out);
    }
}